// round 3
// baseline (speedup 1.0000x reference)
#include <cuda_runtime.h>
#include <math.h>

#define BB 128      // batch
#define HH 1024     // hidden
#define EE 512      // embed
#define SS 256      // src len
#define VV 32000    // vocab
#define KGI (EE + HH)        // 1536
#define KFC (EE + 2 * HH)    // 2560

// ---------------- scratch (device globals; no allocations allowed) ----------
__device__ __align__(16) float g_xemb[BB * EE];
__device__ __align__(16) float g_dw[BB * HH];
__device__ __align__(16) float g_tpos[BB * HH];
__device__ __align__(16) float g_pt[BB];
__device__ __align__(16) float g_energy[BB * SS];   // [b][s]
__device__ __align__(16) float g_ctx[BB * HH];
__device__ __align__(16) float g_gruin[BB * KGI];
__device__ __align__(16) float g_gi[BB * 3 * HH];
__device__ __align__(16) float g_gh[BB * 3 * HH];
__device__ __align__(16) float g_incat[BB * KFC];

__device__ __forceinline__ float warp_sum(float v) {
    #pragma unroll
    for (int o = 16; o; o >>= 1) v += __shfl_xor_sync(0xffffffffu, v, o);
    return v;
}
__device__ __forceinline__ float warp_max(float v) {
    #pragma unroll
    for (int o = 16; o; o >>= 1) v = fmaxf(v, __shfl_xor_sync(0xffffffffu, v, o));
    return v;
}

// ---------------- generic fp32 GEMM: C[M,N] = A[M,K] @ W[N,K]^T + bias ------
// 64x64 tile, BK=16, 256 threads, 4x4 micro-tile. M,N mult of 64; K mult of 16.
__global__ void gemm_kernel(const float* __restrict__ A, const float* __restrict__ W,
                            const float* __restrict__ bias, float* __restrict__ C,
                            int M, int N, int K, int act) {
    __shared__ float As[16][64];
    __shared__ float Ws[16][64];
    const int n0 = blockIdx.x * 64;
    const int m0 = blockIdx.y * 64;
    const int tid = threadIdx.x;
    const int tx = tid & 15;       // n micro index
    const int ty = tid >> 4;       // m micro index
    const int lr = tid >> 2;       // 0..63 row within tile (for loads)
    const int lk = (tid & 3) * 4;  // 0,4,8,12

    const float* Ag = A + (size_t)(m0 + lr) * K + lk;
    const float* Wg = W + (size_t)(n0 + lr) * K + lk;

    float acc[4][4];
    #pragma unroll
    for (int i = 0; i < 4; i++)
        #pragma unroll
        for (int j = 0; j < 4; j++) acc[i][j] = 0.f;

    for (int k0 = 0; k0 < K; k0 += 16) {
        float4 av = *reinterpret_cast<const float4*>(Ag + k0);
        float4 wv = *reinterpret_cast<const float4*>(Wg + k0);
        __syncthreads();
        As[lk + 0][lr] = av.x; As[lk + 1][lr] = av.y;
        As[lk + 2][lr] = av.z; As[lk + 3][lr] = av.w;
        Ws[lk + 0][lr] = wv.x; Ws[lk + 1][lr] = wv.y;
        Ws[lk + 2][lr] = wv.z; Ws[lk + 3][lr] = wv.w;
        __syncthreads();
        #pragma unroll
        for (int kk = 0; kk < 16; kk++) {
            float4 a4 = *reinterpret_cast<const float4*>(&As[kk][ty * 4]);
            float4 w4 = *reinterpret_cast<const float4*>(&Ws[kk][tx * 4]);
            float a[4] = {a4.x, a4.y, a4.z, a4.w};
            float w[4] = {w4.x, w4.y, w4.z, w4.w};
            #pragma unroll
            for (int i = 0; i < 4; i++)
                #pragma unroll
                for (int j = 0; j < 4; j++) acc[i][j] = fmaf(a[i], w[j], acc[i][j]);
        }
    }

    #pragma unroll
    for (int i = 0; i < 4; i++) {
        int m = m0 + ty * 4 + i;
        #pragma unroll
        for (int j = 0; j < 4; j++) {
            int n = n0 + tx * 4 + j;
            float v = acc[i][j] + bias[n];
            if (act == 1) v = tanhf(v);
            C[(size_t)m * N + n] = v;
        }
    }
}

// ---------------- embedding gather -----------------------------------------
__global__ void gather_kernel(const int* __restrict__ x, const float* __restrict__ emb) {
    int idx = blockIdx.x * blockDim.x + threadIdx.x;  // BB*EE
    if (idx >= BB * EE) return;
    int b = idx / EE, e = idx - b * EE;
    g_xemb[idx] = emb[(size_t)x[b] * EE + e];
}

// ---------------- pt & src_len: per-batch block -----------------------------
__global__ void pt_kernel(const float* __restrict__ wproj, const int* __restrict__ masks) {
    int b = blockIdx.x;
    int tid = threadIdx.x;  // 256
    float dot = 0.f;
    for (int i = tid; i < HH; i += 256) dot += g_tpos[b * HH + i] * wproj[i];
    float cnt = (tid < SS) ? (float)masks[tid * BB + b] : 0.f;

    __shared__ float sd[8], sc[8];
    float wd = warp_sum(dot), wc = warp_sum(cnt);
    if ((tid & 31) == 0) { sd[tid >> 5] = wd; sc[tid >> 5] = wc; }
    __syncthreads();
    if (tid == 0) {
        float D = 0.f, Cn = 0.f;
        #pragma unroll
        for (int i = 0; i < 8; i++) { D += sd[i]; Cn += sc[i]; }
        float f = 1.f / (1.f + expf(-D));
        g_pt[b] = (Cn - 1.f) * f;
    }
}

// ---------------- energy[s,b] = tanh(dot(dw[b], enc[s,b,:])) ----------------
__global__ void energy_kernel(const float* __restrict__ enc) {
    int s = blockIdx.x, b = blockIdx.y;
    int tid = threadIdx.x;  // 128
    const float4* e4 = reinterpret_cast<const float4*>(enc + ((size_t)s * BB + b) * HH);
    const float4* d4 = reinterpret_cast<const float4*>(g_dw + b * HH);
    float sum = 0.f;
    for (int i = tid; i < HH / 4; i += 128) {
        float4 a = e4[i], d = d4[i];
        sum += a.x * d.x + a.y * d.y + a.z * d.z + a.w * d.w;
    }
    __shared__ float sm[4];
    float ws = warp_sum(sum);
    if ((tid & 31) == 0) sm[tid >> 5] = ws;
    __syncthreads();
    if (tid == 0) g_energy[b * SS + s] = tanhf(sm[0] + sm[1] + sm[2] + sm[3]);
}

// ---------------- masked softmax * window, then context ---------------------
__global__ void attctx_kernel(const float* __restrict__ enc, const int* __restrict__ masks) {
    int b = blockIdx.x;
    int tid = threadIdx.x;  // 256 == SS
    __shared__ float ws[SS];
    __shared__ float red[8];

    float e = g_energy[b * SS + tid];
    bool mk = masks[tid * BB + b] != 0;
    float val = mk ? e : -1e30f;

    float wm = warp_max(val);
    if ((tid & 31) == 0) red[tid >> 5] = wm;
    __syncthreads();
    float maxv = red[0];
    #pragma unroll
    for (int i = 1; i < 8; i++) maxv = fmaxf(maxv, red[i]);
    __syncthreads();

    float p = expf(val - maxv);
    float wsum = warp_sum(p);
    if ((tid & 31) == 0) red[tid >> 5] = wsum;
    __syncthreads();
    float sum = 0.f;
    #pragma unroll
    for (int i = 0; i < 8; i++) sum += red[i];

    float pt = g_pt[b];
    float sf = (float)tid;
    float diff = pt - sf;
    float win = expf(-(diff * diff) * (1.f / 12.5f));  // sigma = D/2 = 2.5
    float pmaxf = floorf(pt + 5.0f);
    float pminf = floorf(fmaxf(pt - 5.0f, 0.0f));
    float w = (sf < pmaxf && sf >= pminf) ? (p / sum) * win : 0.f;
    ws[tid] = w;
    __syncthreads();

    int slo = (int)pminf;
    int shi = min((int)pmaxf, SS);
    for (int h = tid; h < HH; h += 256) {
        float acc = 0.f;
        for (int s = slo; s < shi; s++)
            acc += ws[s] * enc[((size_t)s * BB + b) * HH + h];
        g_ctx[b * HH + h] = acc;
    }
}

// ---------------- build gru_in = [x_emb, context] ---------------------------
__global__ void gruin_kernel() {
    int idx = blockIdx.x * blockDim.x + threadIdx.x;  // BB*KGI
    if (idx >= BB * KGI) return;
    int b = idx / KGI, k = idx - b * KGI;
    g_gruin[idx] = (k < EE) ? g_xemb[b * EE + k] : g_ctx[b * HH + (k - EE)];
}

// ---------------- GRU combine; also write h_new into out tail & incat -------
__global__ void gru_kernel(const float* __restrict__ phd, float* __restrict__ out,
                           int write_h) {
    int idx = blockIdx.x * blockDim.x + threadIdx.x;  // BB*HH
    if (idx >= BB * HH) return;
    int b = idx / HH, h = idx - b * HH;
    const float* gi = g_gi + b * 3 * HH;
    const float* gh = g_gh + b * 3 * HH;
    float r  = 1.f / (1.f + expf(-(gi[h] + gh[h])));
    float zg = 1.f / (1.f + expf(-(gi[HH + h] + gh[HH + h])));
    float n  = tanhf(gi[2 * HH + h] + r * gh[2 * HH + h]);
    float hp = phd[idx];
    float hn = (1.f - zg) * n + zg * hp;
    g_incat[b * KFC + EE + h] = hn;
    if (write_h) out[(size_t)BB * VV + idx] = hn;
}

// ---------------- fill incat x_emb + context parts --------------------------
__global__ void incat_kernel() {
    int idx = blockIdx.x * blockDim.x + threadIdx.x;  // BB*(EE+HH)
    if (idx >= BB * (EE + HH)) return;
    int b = idx / (EE + HH), k = idx - b * (EE + HH);
    if (k < EE) g_incat[b * KFC + k] = g_xemb[b * EE + k];
    else        g_incat[b * KFC + EE + HH + (k - EE)] = g_ctx[b * HH + (k - EE)];
}

// ---------------- launch -----------------------------------------------------
extern "C" void kernel_launch(void* const* d_in, const int* in_sizes, int n_in,
                              void* d_out, int out_size) {
    const int*   x      = (const int*)d_in[0];
    const float* phd    = (const float*)d_in[1];   // (1,B,H)
    const float* enc    = (const float*)d_in[2];   // (S,B,H)
    const int*   masks  = (const int*)d_in[3];     // (S,B)
    const float* emb    = (const float*)d_in[4];
    const float* W_dec  = (const float*)d_in[5];
    const float* b_dec  = (const float*)d_in[6];
    const float* W_pos  = (const float*)d_in[7];
    const float* b_pos  = (const float*)d_in[8];
    const float* w_proj = (const float*)d_in[9];
    const float* W_ih   = (const float*)d_in[10];
    const float* b_ih   = (const float*)d_in[11];
    const float* W_hh   = (const float*)d_in[12];
    const float* b_hh   = (const float*)d_in[13];
    const float* W_fc   = (const float*)d_in[14];
    const float* b_fc   = (const float*)d_in[15];
    float* out = (float*)d_out;

    float* dwp;    cudaGetSymbolAddress((void**)&dwp, g_dw);
    float* tposp;  cudaGetSymbolAddress((void**)&tposp, g_tpos);
    float* gruinp; cudaGetSymbolAddress((void**)&gruinp, g_gruin);
    float* gip;    cudaGetSymbolAddress((void**)&gip, g_gi);
    float* ghp;    cudaGetSymbolAddress((void**)&ghp, g_gh);
    float* incatp; cudaGetSymbolAddress((void**)&incatp, g_incat);

    int write_h = (out_size >= BB * VV + BB * HH) ? 1 : 0;

    // embedding gather (independent)
    gather_kernel<<<(BB * EE + 255) / 256, 256>>>(x, emb);

    // dw = phd @ W_dec^T + b_dec ; tpos = tanh(phd @ W_pos^T + b_pos)
    gemm_kernel<<<dim3(HH / 64, BB / 64), 256>>>(phd, W_dec, b_dec, dwp, BB, HH, HH, 0);
    gemm_kernel<<<dim3(HH / 64, BB / 64), 256>>>(phd, W_pos, b_pos, tposp, BB, HH, HH, 1);

    // pt and src_len
    pt_kernel<<<BB, 256>>>(w_proj, masks);

    // energy
    energy_kernel<<<dim3(SS, BB), 128>>>(enc);

    // softmax * window, context
    attctx_kernel<<<BB, SS>>>(enc, masks);

    // gru input, gates
    gruin_kernel<<<(BB * KGI + 255) / 256, 256>>>();
    gemm_kernel<<<dim3(3 * HH / 64, BB / 64), 256>>>(gruinp, W_ih, b_ih, gip, BB, 3 * HH, KGI, 0);
    gemm_kernel<<<dim3(3 * HH / 64, BB / 64), 256>>>(phd, W_hh, b_hh, ghp, BB, 3 * HH, HH, 0);

    // combine + fill incat
    gru_kernel<<<(BB * HH + 255) / 256, 256>>>(phd, out, write_h);
    incat_kernel<<<(BB * (EE + HH) + 255) / 256, 256>>>();

    // z = incat @ W_fc^T + b_fc   (dominant GEMM)
    gemm_kernel<<<dim3(VV / 64, BB / 64), 256>>>(incatp, W_fc, b_fc, out, BB, VV, KFC, 0);
}

// round 5
// speedup vs baseline: 1.0534x; 1.0534x over previous
#include <cuda_runtime.h>
#include <math.h>

#define BB 128      // batch
#define HH 1024     // hidden
#define EE 512      // embed
#define SS 256      // src len
#define VV 32000    // vocab
#define KGI (EE + HH)        // 1536
#define KFC (EE + 2 * HH)    // 2560

// ---------------- scratch (device globals; no allocations allowed) ----------
__device__ __align__(16) float g_xemb[BB * EE];
__device__ __align__(16) float g_dw[BB * HH];
__device__ __align__(16) float g_tpos[BB * HH];
__device__ __align__(16) float g_pt[BB];
__device__ __align__(16) float g_energy[BB * SS];   // [b][s]
__device__ __align__(16) float g_ctx[BB * HH];
__device__ __align__(16) float g_gruin[BB * KGI];
__device__ __align__(16) float g_gi[BB * 3 * HH];
__device__ __align__(16) float g_gh[BB * 3 * HH];
__device__ __align__(16) float g_incat[BB * KFC];

__device__ __forceinline__ float warp_sum(float v) {
    #pragma unroll
    for (int o = 16; o; o >>= 1) v += __shfl_xor_sync(0xffffffffu, v, o);
    return v;
}
__device__ __forceinline__ float warp_max(float v) {
    #pragma unroll
    for (int o = 16; o; o >>= 1) v = fmaxf(v, __shfl_xor_sync(0xffffffffu, v, o));
    return v;
}

// ---------------- packed f32x2 helpers (Blackwell FFMA2) --------------------
// Carried in unsigned long long (asm "l" constraint = 64-bit integer reg).
typedef unsigned long long u64;

__device__ __forceinline__ u64 ffma2(u64 a, u64 b, u64 c) {
    u64 d;
    asm("fma.rn.f32x2 %0, %1, %2, %3;" : "=l"(d) : "l"(a), "l"(b), "l"(c));
    return d;
}
__device__ __forceinline__ u64 pack2(float v) {   // {v, v}
    u64 d;
    asm("mov.b64 %0, {%1, %1};" : "=l"(d) : "f"(v));
    return d;
}
__device__ __forceinline__ void unpack2(u64 d, float& lo, float& hi) {
    asm("mov.b64 {%0, %1}, %2;" : "=f"(lo), "=f"(hi) : "l"(d));
}

// ---------------- generic fp32 GEMM: C[M,N] = A[M,K] @ W[N,K]^T + bias ------
// 64x64 tile, BK=16, 256 threads, 4x4 micro-tile, packed f32x2 inner FMAs.
// M,N mult of 64; K mult of 16.
__global__ void gemm_kernel(const float* __restrict__ A, const float* __restrict__ W,
                            const float* __restrict__ bias, float* __restrict__ C,
                            int M, int N, int K, int act) {
    __shared__ __align__(16) float As[16][64];
    __shared__ __align__(16) float Ws[16][64];
    const int n0 = blockIdx.x * 64;
    const int m0 = blockIdx.y * 64;
    const int tid = threadIdx.x;
    const int tx = tid & 15;       // n micro index (4 floats = 2 packed pairs)
    const int ty = tid >> 4;       // m micro index
    const int lr = tid >> 2;       // 0..63 row within tile (for loads)
    const int lk = (tid & 3) * 4;  // 0,4,8,12

    const float* Ag = A + (size_t)(m0 + lr) * K + lk;
    const float* Wg = W + (size_t)(n0 + lr) * K + lk;

    u64 acc2[4][2];
    #pragma unroll
    for (int i = 0; i < 4; i++) { acc2[i][0] = 0ull; acc2[i][1] = 0ull; }

    for (int k0 = 0; k0 < K; k0 += 16) {
        float4 av = *reinterpret_cast<const float4*>(Ag + k0);
        float4 wv = *reinterpret_cast<const float4*>(Wg + k0);
        __syncthreads();
        As[lk + 0][lr] = av.x; As[lk + 1][lr] = av.y;
        As[lk + 2][lr] = av.z; As[lk + 3][lr] = av.w;
        Ws[lk + 0][lr] = wv.x; Ws[lk + 1][lr] = wv.y;
        Ws[lk + 2][lr] = wv.z; Ws[lk + 3][lr] = wv.w;
        __syncthreads();
        #pragma unroll
        for (int kk = 0; kk < 16; kk++) {
            float4 a4 = *reinterpret_cast<const float4*>(&As[kk][ty * 4]);
            ulonglong2 w2 = *reinterpret_cast<const ulonglong2*>(&Ws[kk][tx * 4]);
            u64 a0 = pack2(a4.x), a1 = pack2(a4.y);
            u64 a2 = pack2(a4.z), a3 = pack2(a4.w);
            acc2[0][0] = ffma2(a0, w2.x, acc2[0][0]);
            acc2[0][1] = ffma2(a0, w2.y, acc2[0][1]);
            acc2[1][0] = ffma2(a1, w2.x, acc2[1][0]);
            acc2[1][1] = ffma2(a1, w2.y, acc2[1][1]);
            acc2[2][0] = ffma2(a2, w2.x, acc2[2][0]);
            acc2[2][1] = ffma2(a2, w2.y, acc2[2][1]);
            acc2[3][0] = ffma2(a3, w2.x, acc2[3][0]);
            acc2[3][1] = ffma2(a3, w2.y, acc2[3][1]);
        }
    }

    const int n = n0 + tx * 4;
    const float b0 = bias[n + 0], b1 = bias[n + 1], b2 = bias[n + 2], b3 = bias[n + 3];
    #pragma unroll
    for (int i = 0; i < 4; i++) {
        int m = m0 + ty * 4 + i;
        float v0, v1, v2, v3;
        unpack2(acc2[i][0], v0, v1);
        unpack2(acc2[i][1], v2, v3);
        v0 += b0; v1 += b1; v2 += b2; v3 += b3;
        if (act == 1) { v0 = tanhf(v0); v1 = tanhf(v1); v2 = tanhf(v2); v3 = tanhf(v3); }
        float4 o = make_float4(v0, v1, v2, v3);
        *reinterpret_cast<float4*>(&C[(size_t)m * N + n]) = o;
    }
}

// ---------------- embedding gather -----------------------------------------
__global__ void gather_kernel(const int* __restrict__ x, const float* __restrict__ emb) {
    int idx = blockIdx.x * blockDim.x + threadIdx.x;  // BB*EE
    if (idx >= BB * EE) return;
    int b = idx / EE, e = idx - b * EE;
    g_xemb[idx] = emb[(size_t)x[b] * EE + e];
}

// ---------------- pt & src_len: per-batch block -----------------------------
__global__ void pt_kernel(const float* __restrict__ wproj, const int* __restrict__ masks) {
    int b = blockIdx.x;
    int tid = threadIdx.x;  // 256
    float dot = 0.f;
    for (int i = tid; i < HH; i += 256) dot += g_tpos[b * HH + i] * wproj[i];
    float cnt = (tid < SS) ? (float)masks[tid * BB + b] : 0.f;

    __shared__ float sd[8], sc[8];
    float wd = warp_sum(dot), wc = warp_sum(cnt);
    if ((tid & 31) == 0) { sd[tid >> 5] = wd; sc[tid >> 5] = wc; }
    __syncthreads();
    if (tid == 0) {
        float D = 0.f, Cn = 0.f;
        #pragma unroll
        for (int i = 0; i < 8; i++) { D += sd[i]; Cn += sc[i]; }
        float f = 1.f / (1.f + expf(-D));
        g_pt[b] = (Cn - 1.f) * f;
    }
}

// ---------------- energy[s,b] = tanh(dot(dw[b], enc[s,b,:])) ----------------
__global__ void energy_kernel(const float* __restrict__ enc) {
    int s = blockIdx.x, b = blockIdx.y;
    int tid = threadIdx.x;  // 128
    const float4* e4 = reinterpret_cast<const float4*>(enc + ((size_t)s * BB + b) * HH);
    const float4* d4 = reinterpret_cast<const float4*>(g_dw + b * HH);
    float sum = 0.f;
    for (int i = tid; i < HH / 4; i += 128) {
        float4 a = e4[i], d = d4[i];
        sum += a.x * d.x + a.y * d.y + a.z * d.z + a.w * d.w;
    }
    __shared__ float sm[4];
    float ws = warp_sum(sum);
    if ((tid & 31) == 0) sm[tid >> 5] = ws;
    __syncthreads();
    if (tid == 0) g_energy[b * SS + s] = tanhf(sm[0] + sm[1] + sm[2] + sm[3]);
}

// ---------------- masked softmax * window, then context ---------------------
__global__ void attctx_kernel(const float* __restrict__ enc, const int* __restrict__ masks) {
    int b = blockIdx.x;
    int tid = threadIdx.x;  // 256 == SS
    __shared__ float ws[SS];
    __shared__ float red[8];

    float e = g_energy[b * SS + tid];
    bool mk = masks[tid * BB + b] != 0;
    float val = mk ? e : -1e30f;

    float wm = warp_max(val);
    if ((tid & 31) == 0) red[tid >> 5] = wm;
    __syncthreads();
    float maxv = red[0];
    #pragma unroll
    for (int i = 1; i < 8; i++) maxv = fmaxf(maxv, red[i]);
    __syncthreads();

    float p = expf(val - maxv);
    float wsum = warp_sum(p);
    if ((tid & 31) == 0) red[tid >> 5] = wsum;
    __syncthreads();
    float sum = 0.f;
    #pragma unroll
    for (int i = 0; i < 8; i++) sum += red[i];

    float pt = g_pt[b];
    float sf = (float)tid;
    float diff = pt - sf;
    float win = expf(-(diff * diff) * (1.f / 12.5f));  // sigma = D/2 = 2.5
    float pmaxf = floorf(pt + 5.0f);
    float pminf = floorf(fmaxf(pt - 5.0f, 0.0f));
    float w = (sf < pmaxf && sf >= pminf) ? (p / sum) * win : 0.f;
    ws[tid] = w;
    __syncthreads();

    int slo = (int)pminf;
    int shi = min((int)pmaxf, SS);
    for (int h = tid; h < HH; h += 256) {
        float acc = 0.f;
        for (int s = slo; s < shi; s++)
            acc += ws[s] * enc[((size_t)s * BB + b) * HH + h];
        g_ctx[b * HH + h] = acc;
    }
}

// ---------------- build gru_in = [x_emb, context] ---------------------------
__global__ void gruin_kernel() {
    int idx = blockIdx.x * blockDim.x + threadIdx.x;  // BB*KGI
    if (idx >= BB * KGI) return;
    int b = idx / KGI, k = idx - b * KGI;
    g_gruin[idx] = (k < EE) ? g_xemb[b * EE + k] : g_ctx[b * HH + (k - EE)];
}

// ---------------- GRU combine; also write h_new into out tail & incat -------
__global__ void gru_kernel(const float* __restrict__ phd, float* __restrict__ out,
                           int write_h) {
    int idx = blockIdx.x * blockDim.x + threadIdx.x;  // BB*HH
    if (idx >= BB * HH) return;
    int b = idx / HH, h = idx - b * HH;
    const float* gi = g_gi + b * 3 * HH;
    const float* gh = g_gh + b * 3 * HH;
    float r  = 1.f / (1.f + expf(-(gi[h] + gh[h])));
    float zg = 1.f / (1.f + expf(-(gi[HH + h] + gh[HH + h])));
    float n  = tanhf(gi[2 * HH + h] + r * gh[2 * HH + h]);
    float hp = phd[idx];
    float hn = (1.f - zg) * n + zg * hp;
    g_incat[b * KFC + EE + h] = hn;
    if (write_h) out[(size_t)BB * VV + idx] = hn;
}

// ---------------- fill incat x_emb + context parts --------------------------
__global__ void incat_kernel() {
    int idx = blockIdx.x * blockDim.x + threadIdx.x;  // BB*(EE+HH)
    if (idx >= BB * (EE + HH)) return;
    int b = idx / (EE + HH), k = idx - b * (EE + HH);
    if (k < EE) g_incat[b * KFC + k] = g_xemb[b * EE + k];
    else        g_incat[b * KFC + EE + HH + (k - EE)] = g_ctx[b * HH + (k - EE)];
}

// ---------------- launch -----------------------------------------------------
extern "C" void kernel_launch(void* const* d_in, const int* in_sizes, int n_in,
                              void* d_out, int out_size) {
    const int*   x      = (const int*)d_in[0];
    const float* phd    = (const float*)d_in[1];   // (1,B,H)
    const float* enc    = (const float*)d_in[2];   // (S,B,H)
    const int*   masks  = (const int*)d_in[3];     // (S,B)
    const float* emb    = (const float*)d_in[4];
    const float* W_dec  = (const float*)d_in[5];
    const float* b_dec  = (const float*)d_in[6];
    const float* W_pos  = (const float*)d_in[7];
    const float* b_pos  = (const float*)d_in[8];
    const float* w_proj = (const float*)d_in[9];
    const float* W_ih   = (const float*)d_in[10];
    const float* b_ih   = (const float*)d_in[11];
    const float* W_hh   = (const float*)d_in[12];
    const float* b_hh   = (const float*)d_in[13];
    const float* W_fc   = (const float*)d_in[14];
    const float* b_fc   = (const float*)d_in[15];
    float* out = (float*)d_out;

    float* dwp;    cudaGetSymbolAddress((void**)&dwp, g_dw);
    float* tposp;  cudaGetSymbolAddress((void**)&tposp, g_tpos);
    float* gruinp; cudaGetSymbolAddress((void**)&gruinp, g_gruin);
    float* gip;    cudaGetSymbolAddress((void**)&gip, g_gi);
    float* ghp;    cudaGetSymbolAddress((void**)&ghp, g_gh);
    float* incatp; cudaGetSymbolAddress((void**)&incatp, g_incat);

    int write_h = (out_size >= BB * VV + BB * HH) ? 1 : 0;

    // embedding gather (independent)
    gather_kernel<<<(BB * EE + 255) / 256, 256>>>(x, emb);

    // dw = phd @ W_dec^T + b_dec ; tpos = tanh(phd @ W_pos^T + b_pos)
    gemm_kernel<<<dim3(HH / 64, BB / 64), 256>>>(phd, W_dec, b_dec, dwp, BB, HH, HH, 0);
    gemm_kernel<<<dim3(HH / 64, BB / 64), 256>>>(phd, W_pos, b_pos, tposp, BB, HH, HH, 1);

    // pt and src_len
    pt_kernel<<<BB, 256>>>(w_proj, masks);

    // energy
    energy_kernel<<<dim3(SS, BB), 128>>>(enc);

    // softmax * window, context
    attctx_kernel<<<BB, SS>>>(enc, masks);

    // gru input, gates
    gruin_kernel<<<(BB * KGI + 255) / 256, 256>>>();
    gemm_kernel<<<dim3(3 * HH / 64, BB / 64), 256>>>(gruinp, W_ih, b_ih, gip, BB, 3 * HH, KGI, 0);
    gemm_kernel<<<dim3(3 * HH / 64, BB / 64), 256>>>(phd, W_hh, b_hh, ghp, BB, 3 * HH, HH, 0);

    // combine + fill incat
    gru_kernel<<<(BB * HH + 255) / 256, 256>>>(phd, out, write_h);
    incat_kernel<<<(BB * (EE + HH) + 255) / 256, 256>>>();

    // z = incat @ W_fc^T + b_fc   (dominant GEMM)
    gemm_kernel<<<dim3(VV / 64, BB / 64), 256>>>(incatp, W_fc, b_fc, out, BB, VV, KFC, 0);
}

// round 8
// speedup vs baseline: 1.4627x; 1.3885x over previous
#include <cuda_runtime.h>
#include <cuda_bf16.h>
#include <math.h>
#include <cstdint>

#define BB 128      // batch
#define HH 1024     // hidden
#define EE 512      // embed
#define SS 256      // src len
#define VV 32000    // vocab
#define KGI (EE + HH)        // 1536
#define KFC (EE + 2 * HH)    // 2560

// ---------------- scratch (device globals; no allocations allowed) ----------
__device__ __align__(16) float g_xemb[BB * EE];
__device__ __align__(16) float g_dw[BB * HH];
__device__ __align__(16) float g_tpos[BB * HH];
__device__ __align__(16) float g_pt[BB];
__device__ __align__(16) float g_energy[BB * SS];   // [b][s]
__device__ __align__(16) float g_ctx[BB * HH];
__device__ __align__(16) float g_gruin[BB * KGI];
__device__ __align__(16) float g_gi[BB * 3 * HH];
__device__ __align__(16) float g_gh[BB * 3 * HH];
__device__ __align__(16) float g_incat[BB * KFC];

// bf16-split A operands (hi + residual lo)
__device__ __align__(16) __nv_bfloat16 g_phdH[BB * HH];
__device__ __align__(16) __nv_bfloat16 g_phdL[BB * HH];
__device__ __align__(16) __nv_bfloat16 g_gruinH[BB * KGI];
__device__ __align__(16) __nv_bfloat16 g_gruinL[BB * KGI];
__device__ __align__(16) __nv_bfloat16 g_incatH[BB * KFC];
__device__ __align__(16) __nv_bfloat16 g_incatL[BB * KFC];

__device__ __forceinline__ float warp_sum(float v) {
    #pragma unroll
    for (int o = 16; o; o >>= 1) v += __shfl_xor_sync(0xffffffffu, v, o);
    return v;
}
__device__ __forceinline__ float warp_max(float v) {
    #pragma unroll
    for (int o = 16; o; o >>= 1) v = fmaxf(v, __shfl_xor_sync(0xffffffffu, v, o));
    return v;
}

// ---------------- packed f32x2 helpers (Blackwell FFMA2) --------------------
typedef unsigned long long u64;
__device__ __forceinline__ u64 ffma2(u64 a, u64 b, u64 c) {
    u64 d;
    asm("fma.rn.f32x2 %0, %1, %2, %3;" : "=l"(d) : "l"(a), "l"(b), "l"(c));
    return d;
}
__device__ __forceinline__ u64 pack2(float v) {
    u64 d;
    asm("mov.b64 %0, {%1, %1};" : "=l"(d) : "f"(v));
    return d;
}
__device__ __forceinline__ void unpack2(u64 d, float& lo, float& hi) {
    asm("mov.b64 {%0, %1}, %2;" : "=f"(lo), "=f"(hi) : "l"(d));
}

// bf16x2 pack: {hi half: hf, lo half: lf}
__device__ __forceinline__ uint32_t bf16x2_of(float hf, float lf) {
    uint32_t r;
    asm("cvt.rn.bf16x2.f32 %0, %1, %2;" : "=r"(r) : "f"(hf), "f"(lf));
    return r;
}

// ---------------- HMMA m16n8k16 bf16 ----------------------------------------
__device__ __forceinline__ void mma_bf16(float* acc, const uint32_t* a, const uint32_t* b) {
    asm volatile(
        "mma.sync.aligned.m16n8k16.row.col.f32.bf16.bf16.f32 "
        "{%0,%1,%2,%3}, {%4,%5,%6,%7}, {%8,%9}, {%0,%1,%2,%3};\n"
        : "+f"(acc[0]), "+f"(acc[1]), "+f"(acc[2]), "+f"(acc[3])
        : "r"(a[0]), "r"(a[1]), "r"(a[2]), "r"(a[3]), "r"(b[0]), "r"(b[1]));
}

// ---------------- bf16-split GEMM via mma.sync -------------------------------
// C[128, N] = A[128, K] @ W[N, K]^T + bias ; A pre-split (Ahi/Alo bf16),
// W converted fp32->bf16 hi/lo in-kernel. Grid: N/128 CTAs x 256 threads.
// K mult of 32, N mult of 128.
#define KPAD 48
__global__ void __launch_bounds__(256, 2)
mma_gemm_kernel(const __nv_bfloat16* __restrict__ Ahi, const __nv_bfloat16* __restrict__ Alo,
                const float* __restrict__ W, const float* __restrict__ bias,
                float* __restrict__ C, int N, int K) {
    __shared__ __nv_bfloat16 sAh[128 * KPAD];
    __shared__ __nv_bfloat16 sAl[128 * KPAD];
    __shared__ __nv_bfloat16 sWh[128 * KPAD];
    __shared__ __nv_bfloat16 sWl[128 * KPAD];

    const int tid = threadIdx.x;
    const int lane = tid & 31, warp = tid >> 5;
    const int wm = warp >> 2;            // 0..1 -> M offset wm*64
    const int wn = warp & 3;             // 0..3 -> N offset wn*32
    const int g = lane >> 2, tg = lane & 3;
    const int n0 = blockIdx.x * 128;

    const int row = tid >> 1;            // 0..127 (fill row)
    const int half = (tid & 1) * 16;     // 0 or 16 (fill col base)

    float acc[4][4][4];
    #pragma unroll
    for (int i = 0; i < 4; i++)
        #pragma unroll
        for (int j = 0; j < 4; j++)
            #pragma unroll
            for (int q = 0; q < 4; q++) acc[i][j][q] = 0.f;

    for (int k0 = 0; k0 < K; k0 += 32) {
        // ---- global loads into regs (overlaps previous chunk's MMA) ----
        const uint4* pah = reinterpret_cast<const uint4*>(Ahi + (size_t)row * K + k0 + half);
        const uint4* pal = reinterpret_cast<const uint4*>(Alo + (size_t)row * K + k0 + half);
        uint4 ra0 = pah[0], ra1 = pah[1];
        uint4 rl0 = pal[0], rl1 = pal[1];
        const float4* pw = reinterpret_cast<const float4*>(W + (size_t)(n0 + row) * K + k0 + half);
        uint2 hw[4], lw[4];
        #pragma unroll
        for (int q = 0; q < 4; q++) {
            float4 v = pw[q];
            uint32_t h0 = bf16x2_of(v.y, v.x);
            uint32_t h1 = bf16x2_of(v.w, v.z);
            float rx = v.x - __uint_as_float(h0 << 16);
            float ry = v.y - __uint_as_float(h0 & 0xffff0000u);
            float rz = v.z - __uint_as_float(h1 << 16);
            float rw = v.w - __uint_as_float(h1 & 0xffff0000u);
            hw[q] = make_uint2(h0, h1);
            lw[q] = make_uint2(bf16x2_of(ry, rx), bf16x2_of(rw, rz));
        }

        __syncthreads();   // previous chunk's MMA done reading smem
        *reinterpret_cast<uint4*>(&sAh[row * KPAD + half])     = ra0;
        *reinterpret_cast<uint4*>(&sAh[row * KPAD + half + 8]) = ra1;
        *reinterpret_cast<uint4*>(&sAl[row * KPAD + half])     = rl0;
        *reinterpret_cast<uint4*>(&sAl[row * KPAD + half + 8]) = rl1;
        #pragma unroll
        for (int q = 0; q < 4; q++) {
            *reinterpret_cast<uint2*>(&sWh[row * KPAD + half + q * 4]) = hw[q];
            *reinterpret_cast<uint2*>(&sWl[row * KPAD + half + q * 4]) = lw[q];
        }
        __syncthreads();

        #pragma unroll
        for (int ks = 0; ks < 32; ks += 16) {
            uint32_t bh[4][2], bl[4][2];
            #pragma unroll
            for (int nt = 0; nt < 4; nt++) {
                int br = (wn * 32 + nt * 8 + g) * KPAD + ks + 2 * tg;
                bh[nt][0] = *reinterpret_cast<const uint32_t*>(&sWh[br]);
                bh[nt][1] = *reinterpret_cast<const uint32_t*>(&sWh[br + 8]);
                bl[nt][0] = *reinterpret_cast<const uint32_t*>(&sWl[br]);
                bl[nt][1] = *reinterpret_cast<const uint32_t*>(&sWl[br + 8]);
            }
            #pragma unroll
            for (int mt = 0; mt < 4; mt++) {
                int ar = (wm * 64 + mt * 16 + g) * KPAD + ks + 2 * tg;
                uint32_t ah[4], al[4];
                ah[0] = *reinterpret_cast<const uint32_t*>(&sAh[ar]);
                ah[1] = *reinterpret_cast<const uint32_t*>(&sAh[ar + 8 * KPAD]);
                ah[2] = *reinterpret_cast<const uint32_t*>(&sAh[ar + 8]);
                ah[3] = *reinterpret_cast<const uint32_t*>(&sAh[ar + 8 * KPAD + 8]);
                al[0] = *reinterpret_cast<const uint32_t*>(&sAl[ar]);
                al[1] = *reinterpret_cast<const uint32_t*>(&sAl[ar + 8 * KPAD]);
                al[2] = *reinterpret_cast<const uint32_t*>(&sAl[ar + 8]);
                al[3] = *reinterpret_cast<const uint32_t*>(&sAl[ar + 8 * KPAD + 8]);
                #pragma unroll
                for (int nt = 0; nt < 4; nt++) {
                    mma_bf16(acc[mt][nt], ah, bh[nt]);   // Ah*Wh
                    mma_bf16(acc[mt][nt], ah, bl[nt]);   // Ah*Wl
                    mma_bf16(acc[mt][nt], al, bh[nt]);   // Al*Wh
                }
            }
        }
    }

    // ---- epilogue: direct register->global ----
    #pragma unroll
    for (int mt = 0; mt < 4; mt++) {
        int m = wm * 64 + mt * 16 + g;
        #pragma unroll
        for (int nt = 0; nt < 4; nt++) {
            int col = n0 + wn * 32 + nt * 8 + 2 * tg;
            float2 bv = *reinterpret_cast<const float2*>(&bias[col]);
            float2 o0 = make_float2(acc[mt][nt][0] + bv.x, acc[mt][nt][1] + bv.y);
            float2 o1 = make_float2(acc[mt][nt][2] + bv.x, acc[mt][nt][3] + bv.y);
            *reinterpret_cast<float2*>(&C[(size_t)m * N + col]) = o0;
            *reinterpret_cast<float2*>(&C[(size_t)(m + 8) * N + col]) = o1;
        }
    }
}

// ---------------- A split prepass: fp32 -> bf16 hi/lo -----------------------
__global__ void conv_a_kernel(const float* __restrict__ src, __nv_bfloat16* __restrict__ hi,
                              __nv_bfloat16* __restrict__ lo, int n2) {
    int i = blockIdx.x * 256 + threadIdx.x;
    if (i >= n2) return;
    float2 v = reinterpret_cast<const float2*>(src)[i];
    uint32_t h = bf16x2_of(v.y, v.x);
    float rx = v.x - __uint_as_float(h << 16);
    float ry = v.y - __uint_as_float(h & 0xffff0000u);
    uint32_t l = bf16x2_of(ry, rx);
    reinterpret_cast<uint32_t*>(hi)[i] = h;
    reinterpret_cast<uint32_t*>(lo)[i] = l;
}

// ---------------- fp32 FFMA2 GEMM (exact path, used for W_pos) --------------
__global__ void gemm_kernel(const float* __restrict__ A, const float* __restrict__ W,
                            const float* __restrict__ bias, float* __restrict__ C,
                            int M, int N, int K, int act) {
    __shared__ __align__(16) float As[16][64];
    __shared__ __align__(16) float Ws[16][64];
    const int n0 = blockIdx.x * 64;
    const int m0 = blockIdx.y * 64;
    const int tid = threadIdx.x;
    const int tx = tid & 15;
    const int ty = tid >> 4;
    const int lr = tid >> 2;
    const int lk = (tid & 3) * 4;

    const float* Ag = A + (size_t)(m0 + lr) * K + lk;
    const float* Wg = W + (size_t)(n0 + lr) * K + lk;

    u64 acc2[4][2];
    #pragma unroll
    for (int i = 0; i < 4; i++) { acc2[i][0] = 0ull; acc2[i][1] = 0ull; }

    for (int k0 = 0; k0 < K; k0 += 16) {
        float4 av = *reinterpret_cast<const float4*>(Ag + k0);
        float4 wv = *reinterpret_cast<const float4*>(Wg + k0);
        __syncthreads();
        As[lk + 0][lr] = av.x; As[lk + 1][lr] = av.y;
        As[lk + 2][lr] = av.z; As[lk + 3][lr] = av.w;
        Ws[lk + 0][lr] = wv.x; Ws[lk + 1][lr] = wv.y;
        Ws[lk + 2][lr] = wv.z; Ws[lk + 3][lr] = wv.w;
        __syncthreads();
        #pragma unroll
        for (int kk = 0; kk < 16; kk++) {
            float4 a4 = *reinterpret_cast<const float4*>(&As[kk][ty * 4]);
            ulonglong2 w2 = *reinterpret_cast<const ulonglong2*>(&Ws[kk][tx * 4]);
            u64 a0 = pack2(a4.x), a1 = pack2(a4.y);
            u64 a2 = pack2(a4.z), a3 = pack2(a4.w);
            acc2[0][0] = ffma2(a0, w2.x, acc2[0][0]);
            acc2[0][1] = ffma2(a0, w2.y, acc2[0][1]);
            acc2[1][0] = ffma2(a1, w2.x, acc2[1][0]);
            acc2[1][1] = ffma2(a1, w2.y, acc2[1][1]);
            acc2[2][0] = ffma2(a2, w2.x, acc2[2][0]);
            acc2[2][1] = ffma2(a2, w2.y, acc2[2][1]);
            acc2[3][0] = ffma2(a3, w2.x, acc2[3][0]);
            acc2[3][1] = ffma2(a3, w2.y, acc2[3][1]);
        }
    }

    const int n = n0 + tx * 4;
    const float b0 = bias[n + 0], b1 = bias[n + 1], b2 = bias[n + 2], b3 = bias[n + 3];
    #pragma unroll
    for (int i = 0; i < 4; i++) {
        int m = m0 + ty * 4 + i;
        float v0, v1, v2, v3;
        unpack2(acc2[i][0], v0, v1);
        unpack2(acc2[i][1], v2, v3);
        v0 += b0; v1 += b1; v2 += b2; v3 += b3;
        if (act == 1) { v0 = tanhf(v0); v1 = tanhf(v1); v2 = tanhf(v2); v3 = tanhf(v3); }
        *reinterpret_cast<float4*>(&C[(size_t)m * N + n]) = make_float4(v0, v1, v2, v3);
    }
}

// ---------------- embedding gather ------------------------------------------
__global__ void gather_kernel(const int* __restrict__ x, const float* __restrict__ emb) {
    int idx = blockIdx.x * blockDim.x + threadIdx.x;
    if (idx >= BB * EE) return;
    int b = idx / EE, e = idx - b * EE;
    g_xemb[idx] = emb[(size_t)x[b] * EE + e];
}

// ---------------- pt & src_len ----------------------------------------------
__global__ void pt_kernel(const float* __restrict__ wproj, const int* __restrict__ masks) {
    int b = blockIdx.x;
    int tid = threadIdx.x;  // 256
    float dot = 0.f;
    for (int i = tid; i < HH; i += 256) dot += g_tpos[b * HH + i] * wproj[i];
    float cnt = (tid < SS) ? (float)masks[tid * BB + b] : 0.f;

    __shared__ float sd[8], sc[8];
    float wd = warp_sum(dot), wc = warp_sum(cnt);
    if ((tid & 31) == 0) { sd[tid >> 5] = wd; sc[tid >> 5] = wc; }
    __syncthreads();
    if (tid == 0) {
        float D = 0.f, Cn = 0.f;
        #pragma unroll
        for (int i = 0; i < 8; i++) { D += sd[i]; Cn += sc[i]; }
        float f = 1.f / (1.f + expf(-D));
        g_pt[b] = (Cn - 1.f) * f;
    }
}

// ---------------- energy[s,b] = tanh(dot(dw[b], enc[s,b,:])) -----------------
__global__ void energy_kernel(const float* __restrict__ enc) {
    int s = blockIdx.x, b = blockIdx.y;
    int tid = threadIdx.x;  // 128
    const float4* e4 = reinterpret_cast<const float4*>(enc + ((size_t)s * BB + b) * HH);
    const float4* d4 = reinterpret_cast<const float4*>(g_dw + b * HH);
    float sum = 0.f;
    for (int i = tid; i < HH / 4; i += 128) {
        float4 a = e4[i], d = d4[i];
        sum += a.x * d.x + a.y * d.y + a.z * d.z + a.w * d.w;
    }
    __shared__ float sm[4];
    float ws = warp_sum(sum);
    if ((tid & 31) == 0) sm[tid >> 5] = ws;
    __syncthreads();
    if (tid == 0) g_energy[b * SS + s] = tanhf(sm[0] + sm[1] + sm[2] + sm[3]);
}

// ---------------- masked softmax * window, then context ----------------------
__global__ void attctx_kernel(const float* __restrict__ enc, const int* __restrict__ masks) {
    int b = blockIdx.x;
    int tid = threadIdx.x;  // 256 == SS
    __shared__ float ws[SS];
    __shared__ float red[8];

    float e = g_energy[b * SS + tid];
    bool mk = masks[tid * BB + b] != 0;
    float val = mk ? e : -1e30f;

    float wm = warp_max(val);
    if ((tid & 31) == 0) red[tid >> 5] = wm;
    __syncthreads();
    float maxv = red[0];
    #pragma unroll
    for (int i = 1; i < 8; i++) maxv = fmaxf(maxv, red[i]);
    __syncthreads();

    float p = expf(val - maxv);
    float wsum = warp_sum(p);
    if ((tid & 31) == 0) red[tid >> 5] = wsum;
    __syncthreads();
    float sum = 0.f;
    #pragma unroll
    for (int i = 0; i < 8; i++) sum += red[i];

    float pt = g_pt[b];
    float sf = (float)tid;
    float diff = pt - sf;
    float win = expf(-(diff * diff) * (1.f / 12.5f));
    float pmaxf = floorf(pt + 5.0f);
    float pminf = floorf(fmaxf(pt - 5.0f, 0.0f));
    float w = (sf < pmaxf && sf >= pminf) ? (p / sum) * win : 0.f;
    ws[tid] = w;
    __syncthreads();

    int slo = (int)pminf;
    int shi = min((int)pmaxf, SS);
    for (int h = tid; h < HH; h += 256) {
        float acc = 0.f;
        for (int s = slo; s < shi; s++)
            acc += ws[s] * enc[((size_t)s * BB + b) * HH + h];
        g_ctx[b * HH + h] = acc;
    }
}

// ---------------- build gru_in = [x_emb, context] ----------------------------
__global__ void gruin_kernel() {
    int idx = blockIdx.x * blockDim.x + threadIdx.x;
    if (idx >= BB * KGI) return;
    int b = idx / KGI, k = idx - b * KGI;
    g_gruin[idx] = (k < EE) ? g_xemb[b * EE + k] : g_ctx[b * HH + (k - EE)];
}

// ---------------- GRU combine ------------------------------------------------
__global__ void gru_kernel(const float* __restrict__ phd, float* __restrict__ out,
                           int write_h) {
    int idx = blockIdx.x * blockDim.x + threadIdx.x;
    if (idx >= BB * HH) return;
    int b = idx / HH, h = idx - b * HH;
    const float* gi = g_gi + b * 3 * HH;
    const float* gh = g_gh + b * 3 * HH;
    float r  = 1.f / (1.f + expf(-(gi[h] + gh[h])));
    float zg = 1.f / (1.f + expf(-(gi[HH + h] + gh[HH + h])));
    float n  = tanhf(gi[2 * HH + h] + r * gh[2 * HH + h]);
    float hp = phd[idx];
    float hn = (1.f - zg) * n + zg * hp;
    g_incat[b * KFC + EE + h] = hn;
    if (write_h) out[(size_t)BB * VV + idx] = hn;
}

// ---------------- fill incat x_emb + context parts ---------------------------
__global__ void incat_kernel() {
    int idx = blockIdx.x * blockDim.x + threadIdx.x;
    if (idx >= BB * (EE + HH)) return;
    int b = idx / (EE + HH), k = idx - b * (EE + HH);
    if (k < EE) g_incat[b * KFC + k] = g_xemb[b * EE + k];
    else        g_incat[b * KFC + EE + HH + (k - EE)] = g_ctx[b * HH + (k - EE)];
}

// ---------------- launch -----------------------------------------------------
extern "C" void kernel_launch(void* const* d_in, const int* in_sizes, int n_in,
                              void* d_out, int out_size) {
    const int*   x      = (const int*)d_in[0];
    const float* phd    = (const float*)d_in[1];
    const float* enc    = (const float*)d_in[2];
    const int*   masks  = (const int*)d_in[3];
    const float* emb    = (const float*)d_in[4];
    const float* W_dec  = (const float*)d_in[5];
    const float* b_dec  = (const float*)d_in[6];
    const float* W_pos  = (const float*)d_in[7];
    const float* b_pos  = (const float*)d_in[8];
    const float* w_proj = (const float*)d_in[9];
    const float* W_ih   = (const float*)d_in[10];
    const float* b_ih   = (const float*)d_in[11];
    const float* W_hh   = (const float*)d_in[12];
    const float* b_hh   = (const float*)d_in[13];
    const float* W_fc   = (const float*)d_in[14];
    const float* b_fc   = (const float*)d_in[15];
    float* out = (float*)d_out;

    float* dwp;    cudaGetSymbolAddress((void**)&dwp, g_dw);
    float* tposp;  cudaGetSymbolAddress((void**)&tposp, g_tpos);
    float* gruinp; cudaGetSymbolAddress((void**)&gruinp, g_gruin);
    float* gip;    cudaGetSymbolAddress((void**)&gip, g_gi);
    float* ghp;    cudaGetSymbolAddress((void**)&ghp, g_gh);
    float* incatp; cudaGetSymbolAddress((void**)&incatp, g_incat);
    __nv_bfloat16 *phdH, *phdL, *gruH, *gruL, *incH, *incL;
    cudaGetSymbolAddress((void**)&phdH, g_phdH);
    cudaGetSymbolAddress((void**)&phdL, g_phdL);
    cudaGetSymbolAddress((void**)&gruH, g_gruinH);
    cudaGetSymbolAddress((void**)&gruL, g_gruinL);
    cudaGetSymbolAddress((void**)&incH, g_incatH);
    cudaGetSymbolAddress((void**)&incL, g_incatL);

    int write_h = (out_size >= BB * VV + BB * HH) ? 1 : 0;

    gather_kernel<<<(BB * EE + 255) / 256, 256>>>(x, emb);

    // split phd -> bf16 hi/lo
    conv_a_kernel<<<(BB * HH / 2 + 255) / 256, 256>>>(phd, phdH, phdL, BB * HH / 2);

    // dw = phd @ W_dec^T (mma); tpos = tanh(phd @ W_pos^T) (exact fp32 path)
    mma_gemm_kernel<<<HH / 128, 256>>>(phdH, phdL, W_dec, b_dec, dwp, HH, HH);
    gemm_kernel<<<dim3(HH / 64, BB / 64), 256>>>(phd, W_pos, b_pos, tposp, BB, HH, HH, 1);

    pt_kernel<<<BB, 256>>>(w_proj, masks);
    energy_kernel<<<dim3(SS, BB), 128>>>(enc);
    attctx_kernel<<<BB, SS>>>(enc, masks);

    gruin_kernel<<<(BB * KGI + 255) / 256, 256>>>();
    conv_a_kernel<<<(BB * KGI / 2 + 255) / 256, 256>>>(gruinp, gruH, gruL, BB * KGI / 2);
    mma_gemm_kernel<<<3 * HH / 128, 256>>>(gruH, gruL, W_ih, b_ih, gip, 3 * HH, KGI);
    mma_gemm_kernel<<<3 * HH / 128, 256>>>(phdH, phdL, W_hh, b_hh, ghp, 3 * HH, HH);

    gru_kernel<<<(BB * HH + 255) / 256, 256>>>(phd, out, write_h);
    incat_kernel<<<(BB * (EE + HH) + 255) / 256, 256>>>();
    conv_a_kernel<<<(BB * KFC / 2 + 255) / 256, 256>>>(incatp, incH, incL, BB * KFC / 2);

    // z = incat @ W_fc^T + b_fc  (dominant, mma.sync bf16 3-term)
    mma_gemm_kernel<<<VV / 128, 256>>>(incH, incL, W_fc, b_fc, out, VV, KFC);
}

// round 17
// speedup vs baseline: 2.4023x; 1.6424x over previous
#include <cuda_runtime.h>
#include <cuda_bf16.h>
#include <math.h>
#include <cstdint>

#define BB 128      // batch
#define HH 1024     // hidden
#define EE 512      // embed
#define SS 256      // src len
#define VV 32000    // vocab
#define KGI (EE + HH)        // 1536
#define KFC (EE + 2 * HH)    // 2560

// ---------------- scratch (device globals; no allocations allowed) ----------
__device__ __align__(16) float g_xemb[BB * EE];
__device__ __align__(16) float g_dw[BB * HH];
__device__ __align__(16) float g_tpos[BB * HH];
__device__ __align__(16) float g_tpart[4 * BB * HH];
__device__ __align__(16) float g_pt[BB];
__device__ __align__(16) float g_energy[BB * SS];   // [b][s]
__device__ __align__(16) float g_ctx[BB * HH];
__device__ __align__(16) float g_gruin[BB * KGI];
__device__ __align__(16) float g_gi[BB * 3 * HH];
__device__ __align__(16) float g_gh[BB * 3 * HH];
__device__ __align__(16) float g_incat[BB * KFC];

// bf16-split A operands (hi + residual lo)
__device__ __align__(16) __nv_bfloat16 g_phdH[BB * HH];
__device__ __align__(16) __nv_bfloat16 g_phdL[BB * HH];
__device__ __align__(16) __nv_bfloat16 g_gruinH[BB * KGI];
__device__ __align__(16) __nv_bfloat16 g_gruinL[BB * KGI];
__device__ __align__(16) __nv_bfloat16 g_incatH[BB * KFC];
__device__ __align__(16) __nv_bfloat16 g_incatL[BB * KFC];

__device__ __forceinline__ float warp_sum(float v) {
    #pragma unroll
    for (int o = 16; o; o >>= 1) v += __shfl_xor_sync(0xffffffffu, v, o);
    return v;
}
__device__ __forceinline__ float warp_max(float v) {
    #pragma unroll
    for (int o = 16; o; o >>= 1) v = fmaxf(v, __shfl_xor_sync(0xffffffffu, v, o));
    return v;
}

// ---------------- packed f32x2 helpers (Blackwell FFMA2) --------------------
typedef unsigned long long u64;
__device__ __forceinline__ u64 ffma2(u64 a, u64 b, u64 c) {
    u64 d;
    asm("fma.rn.f32x2 %0, %1, %2, %3;" : "=l"(d) : "l"(a), "l"(b), "l"(c));
    return d;
}
__device__ __forceinline__ u64 pack2(float v) {
    u64 d;
    asm("mov.b64 %0, {%1, %1};" : "=l"(d) : "f"(v));
    return d;
}
__device__ __forceinline__ void unpack2(u64 d, float& lo, float& hi) {
    asm("mov.b64 {%0, %1}, %2;" : "=f"(lo), "=f"(hi) : "l"(d));
}

// bf16x2 pack: {hi half: hf, lo half: lf}
__device__ __forceinline__ uint32_t bf16x2_of(float hf, float lf) {
    uint32_t r;
    asm("cvt.rn.bf16x2.f32 %0, %1, %2;" : "=r"(r) : "f"(hf), "f"(lf));
    return r;
}

__device__ __forceinline__ uint32_t smem_u32(const void* p) {
    uint32_t a;
    asm("{ .reg .u64 t; cvta.to.shared.u64 t, %1; cvt.u32.u64 %0, t; }" : "=r"(a) : "l"(p));
    return a;
}
__device__ __forceinline__ void cp16(uint32_t saddr, const void* g) {
    asm volatile("cp.async.cg.shared.global [%0], [%1], 16;" :: "r"(saddr), "l"(g));
}

// ---------------- HMMA m16n8k16 bf16 ----------------------------------------
__device__ __forceinline__ void mma_bf16(float* acc, const uint32_t* a, const uint32_t* b) {
    asm volatile(
        "mma.sync.aligned.m16n8k16.row.col.f32.bf16.bf16.f32 "
        "{%0,%1,%2,%3}, {%4,%5,%6,%7}, {%8,%9}, {%0,%1,%2,%3};\n"
        : "+f"(acc[0]), "+f"(acc[1]), "+f"(acc[2]), "+f"(acc[3])
        : "r"(a[0]), "r"(a[1]), "r"(a[2]), "r"(a[3]), "r"(b[0]), "r"(b[1]));
}
__device__ __forceinline__ void ldm4(uint32_t* a, uint32_t addr) {
    asm volatile("ldmatrix.sync.aligned.m8n8.x4.shared.b16 {%0,%1,%2,%3}, [%4];"
                 : "=r"(a[0]), "=r"(a[1]), "=r"(a[2]), "=r"(a[3]) : "r"(addr));
}

// ---------------- bf16-split pipelined GEMM via mma.sync ---------------------
// C[128, N] = A[128, K] @ W[N, K]^T + bias. A pre-split bf16 hi/lo; W fp32
// staged via cp.async, converted to bf16 hi/lo at fragment build.
// Grid: N/128 CTAs x 256 threads. K mult of 64, N mult of 128.
#define BKK 64
#define A_STRIDE 72                 // bf16 elems/row: 144 B = 16*9 (cp.async ok)
#define W_STRIDE 72                 // fp32 elems/row: 288 B = 16*18 (cp.async ok)
#define SZ_AH (128 * A_STRIDE * 2)  // 18432 B
#define SZ_W  (128 * W_STRIDE * 4)  // 36864 B
#define STG_BYTES (2 * SZ_AH + SZ_W) // 73728 B
#define SMEM_MMA (2 * STG_BYTES)     // 147456 B

__global__ void __launch_bounds__(256, 1)
mma_gemm_kernel(const __nv_bfloat16* __restrict__ Ahi, const __nv_bfloat16* __restrict__ Alo,
                const float* __restrict__ W, const float* __restrict__ bias,
                float* __restrict__ C, int N, int K) {
    extern __shared__ char smem[];
    const uint32_t sbase = smem_u32(smem);
    const int tid = threadIdx.x;
    const int lane = tid & 31, warp = tid >> 5;
    const int wm = warp >> 2, wn = warp & 3;
    const int g = lane >> 2, tg = lane & 3;
    const int n0 = blockIdx.x * 128;

    // ldmatrix lane address components
    const int sel = lane >> 3, lr8 = lane & 7;
    const int lrow = (sel & 1) * 8 + lr8;
    const int lcol = (sel >> 1) * 8;

    float acc[4][4][4];
    #pragma unroll
    for (int i = 0; i < 4; i++)
        #pragma unroll
        for (int j = 0; j < 4; j++)
            #pragma unroll
            for (int q = 0; q < 4; q++) acc[i][j][q] = 0.f;

    // --- stage copy: chunk at k0 into stage s ---
    auto stage_copy = [&](int s, int k0) {
        uint32_t sAh = sbase + s * STG_BYTES;
        uint32_t sAl = sAh + SZ_AH;
        uint32_t sW  = sAl + SZ_AH;
        #pragma unroll
        for (int i = 0; i < 4; i++) {
            int idx = tid + i * 256;
            int row = idx >> 3, cc = idx & 7;
            uint32_t so = (uint32_t)(row * A_STRIDE + cc * 8) * 2;
            size_t go = (size_t)row * K + k0 + cc * 8;
            cp16(sAh + so, Ahi + go);
            cp16(sAl + so, Alo + go);
        }
        #pragma unroll
        for (int i = 0; i < 8; i++) {
            int idx = tid + i * 256;
            int row = idx >> 4, cc = idx & 15;
            cp16(sW + (uint32_t)(row * W_STRIDE + cc * 4) * 4,
                 W + (size_t)(n0 + row) * K + k0 + cc * 4);
        }
    };

    const int nk = K / BKK;
    stage_copy(0, 0);
    asm volatile("cp.async.commit_group;");

    for (int ck = 0; ck < nk; ck++) {
        if (ck + 1 < nk) {
            stage_copy((ck + 1) & 1, (ck + 1) * BKK);
            asm volatile("cp.async.commit_group;");
            asm volatile("cp.async.wait_group 1;");
        } else {
            asm volatile("cp.async.wait_group 0;");
        }
        __syncthreads();

        const int s = ck & 1;
        const uint32_t sAh = sbase + s * STG_BYTES;
        const uint32_t sAl = sAh + SZ_AH;
        const uint32_t sW  = sAl + SZ_AH;

        #pragma unroll
        for (int ks = 0; ks < BKK; ks += 16) {
            // build B fragments (hi & lo) from fp32 W smem
            uint32_t bh[4][2], bl[4][2];
            #pragma unroll
            for (int nt = 0; nt < 4; nt++) {
                int n = wn * 32 + nt * 8 + g;
                uint32_t a0 = sW + (uint32_t)(n * W_STRIDE + ks + 2 * tg) * 4;
                float x0, y0, x1, y1;
                asm volatile("ld.shared.v2.f32 {%0,%1}, [%2];" : "=f"(x0), "=f"(y0) : "r"(a0));
                asm volatile("ld.shared.v2.f32 {%0,%1}, [%2];" : "=f"(x1), "=f"(y1) : "r"(a0 + 32));
                uint32_t h0 = bf16x2_of(y0, x0);
                uint32_t h1 = bf16x2_of(y1, x1);
                float rx0 = x0 - __uint_as_float(h0 << 16);
                float ry0 = y0 - __uint_as_float(h0 & 0xffff0000u);
                float rx1 = x1 - __uint_as_float(h1 << 16);
                float ry1 = y1 - __uint_as_float(h1 & 0xffff0000u);
                bh[nt][0] = h0; bh[nt][1] = h1;
                bl[nt][0] = bf16x2_of(ry0, rx0);
                bl[nt][1] = bf16x2_of(ry1, rx1);
            }
            #pragma unroll
            for (int mt = 0; mt < 4; mt++) {
                int mrow = wm * 64 + mt * 16;
                uint32_t ao = (uint32_t)((mrow + lrow) * A_STRIDE + ks + lcol) * 2;
                uint32_t ah[4], al[4];
                ldm4(ah, sAh + ao);
                ldm4(al, sAl + ao);
                #pragma unroll
                for (int nt = 0; nt < 4; nt++) {
                    mma_bf16(acc[mt][nt], ah, bh[nt]);   // Ah*Wh
                    mma_bf16(acc[mt][nt], ah, bl[nt]);   // Ah*Wl
                    mma_bf16(acc[mt][nt], al, bh[nt]);   // Al*Wh
                }
            }
        }
        __syncthreads();
    }

    // ---- epilogue ----
    #pragma unroll
    for (int mt = 0; mt < 4; mt++) {
        int m = wm * 64 + mt * 16 + g;
        #pragma unroll
        for (int nt = 0; nt < 4; nt++) {
            int col = n0 + wn * 32 + nt * 8 + 2 * tg;
            float2 bv = *reinterpret_cast<const float2*>(&bias[col]);
            float2 o0 = make_float2(acc[mt][nt][0] + bv.x, acc[mt][nt][1] + bv.y);
            float2 o1 = make_float2(acc[mt][nt][2] + bv.x, acc[mt][nt][3] + bv.y);
            *reinterpret_cast<float2*>(&C[(size_t)m * N + col]) = o0;
            *reinterpret_cast<float2*>(&C[(size_t)(m + 8) * N + col]) = o1;
        }
    }
}

// ---------------- A split prepass: fp32 -> bf16 hi/lo -----------------------
__global__ void conv_a_kernel(const float* __restrict__ src, __nv_bfloat16* __restrict__ hi,
                              __nv_bfloat16* __restrict__ lo, int n2) {
    int i = blockIdx.x * 256 + threadIdx.x;
    if (i >= n2) return;
    float2 v = reinterpret_cast<const float2*>(src)[i];
    uint32_t h = bf16x2_of(v.y, v.x);
    float rx = v.x - __uint_as_float(h << 16);
    float ry = v.y - __uint_as_float(h & 0xffff0000u);
    uint32_t l = bf16x2_of(ry, rx);
    reinterpret_cast<uint32_t*>(hi)[i] = h;
    reinterpret_cast<uint32_t*>(lo)[i] = l;
}

// ---------------- fp32 FFMA2 split-K GEMM (exact path for W_pos) ------------
__global__ void gemm_part_kernel(const float* __restrict__ A, const float* __restrict__ W,
                                 float* __restrict__ Cpart, int M, int N, int K) {
    __shared__ __align__(16) float As[16][64];
    __shared__ __align__(16) float Ws[16][64];
    const int n0 = blockIdx.x * 64;
    const int m0 = blockIdx.y * 64;
    const int kb = blockIdx.z * 256;
    const int tid = threadIdx.x;
    const int tx = tid & 15;
    const int ty = tid >> 4;
    const int lr = tid >> 2;
    const int lk = (tid & 3) * 4;

    const float* Ag = A + (size_t)(m0 + lr) * K + lk + kb;
    const float* Wg = W + (size_t)(n0 + lr) * K + lk + kb;

    u64 acc2[4][2];
    #pragma unroll
    for (int i = 0; i < 4; i++) { acc2[i][0] = 0ull; acc2[i][1] = 0ull; }

    for (int k0 = 0; k0 < 256; k0 += 16) {
        float4 av = *reinterpret_cast<const float4*>(Ag + k0);
        float4 wv = *reinterpret_cast<const float4*>(Wg + k0);
        __syncthreads();
        As[lk + 0][lr] = av.x; As[lk + 1][lr] = av.y;
        As[lk + 2][lr] = av.z; As[lk + 3][lr] = av.w;
        Ws[lk + 0][lr] = wv.x; Ws[lk + 1][lr] = wv.y;
        Ws[lk + 2][lr] = wv.z; Ws[lk + 3][lr] = wv.w;
        __syncthreads();
        #pragma unroll
        for (int kk = 0; kk < 16; kk++) {
            float4 a4 = *reinterpret_cast<const float4*>(&As[kk][ty * 4]);
            ulonglong2 w2 = *reinterpret_cast<const ulonglong2*>(&Ws[kk][tx * 4]);
            u64 a0 = pack2(a4.x), a1 = pack2(a4.y);
            u64 a2 = pack2(a4.z), a3 = pack2(a4.w);
            acc2[0][0] = ffma2(a0, w2.x, acc2[0][0]);
            acc2[0][1] = ffma2(a0, w2.y, acc2[0][1]);
            acc2[1][0] = ffma2(a1, w2.x, acc2[1][0]);
            acc2[1][1] = ffma2(a1, w2.y, acc2[1][1]);
            acc2[2][0] = ffma2(a2, w2.x, acc2[2][0]);
            acc2[2][1] = ffma2(a2, w2.y, acc2[2][1]);
            acc2[3][0] = ffma2(a3, w2.x, acc2[3][0]);
            acc2[3][1] = ffma2(a3, w2.y, acc2[3][1]);
        }
    }

    float* Cz = Cpart + (size_t)blockIdx.z * M * N;
    const int n = n0 + tx * 4;
    #pragma unroll
    for (int i = 0; i < 4; i++) {
        int m = m0 + ty * 4 + i;
        float v0, v1, v2, v3;
        unpack2(acc2[i][0], v0, v1);
        unpack2(acc2[i][1], v2, v3);
        *reinterpret_cast<float4*>(&Cz[(size_t)m * N + n]) = make_float4(v0, v1, v2, v3);
    }
}

__global__ void reduce_tanh_kernel(const float* __restrict__ bias) {
    int i = blockIdx.x * 256 + threadIdx.x;
    if (i >= BB * HH) return;
    int n = i & (HH - 1);
    float s = g_tpart[i] + g_tpart[BB * HH + i];
    float t = g_tpart[2 * BB * HH + i] + g_tpart[3 * BB * HH + i];
    g_tpos[i] = tanhf(s + t + bias[n]);
}

// ---------------- embedding gather ------------------------------------------
__global__ void gather_kernel(const int* __restrict__ x, const float* __restrict__ emb) {
    int idx = blockIdx.x * blockDim.x + threadIdx.x;
    if (idx >= BB * EE) return;
    int b = idx / EE, e = idx - b * EE;
    g_xemb[idx] = emb[(size_t)x[b] * EE + e];
}

// ---------------- pt & src_len ----------------------------------------------
__global__ void pt_kernel(const float* __restrict__ wproj, const int* __restrict__ masks) {
    int b = blockIdx.x;
    int tid = threadIdx.x;  // 256
    float dot = 0.f;
    for (int i = tid; i < HH; i += 256) dot += g_tpos[b * HH + i] * wproj[i];
    float cnt = (tid < SS) ? (float)masks[tid * BB + b] : 0.f;

    __shared__ float sd[8], sc[8];
    float wd = warp_sum(dot), wc = warp_sum(cnt);
    if ((tid & 31) == 0) { sd[tid >> 5] = wd; sc[tid >> 5] = wc; }
    __syncthreads();
    if (tid == 0) {
        float D = 0.f, Cn = 0.f;
        #pragma unroll
        for (int i = 0; i < 8; i++) { D += sd[i]; Cn += sc[i]; }
        float f = 1.f / (1.f + expf(-D));
        g_pt[b] = (Cn - 1.f) * f;
    }
}

// ---------------- energy[s,b] = tanh(dot(dw[b], enc[s,b,:])) -----------------
__global__ void energy_kernel(const float* __restrict__ enc) {
    int s = blockIdx.x, b = blockIdx.y;
    int tid = threadIdx.x;  // 128
    const float4* e4 = reinterpret_cast<const float4*>(enc + ((size_t)s * BB + b) * HH);
    const float4* d4 = reinterpret_cast<const float4*>(g_dw + b * HH);
    float sum = 0.f;
    for (int i = tid; i < HH / 4; i += 128) {
        float4 a = e4[i], d = d4[i];
        sum += a.x * d.x + a.y * d.y + a.z * d.z + a.w * d.w;
    }
    __shared__ float sm[4];
    float ws = warp_sum(sum);
    if ((tid & 31) == 0) sm[tid >> 5] = ws;
    __syncthreads();
    if (tid == 0) g_energy[b * SS + s] = tanhf(sm[0] + sm[1] + sm[2] + sm[3]);
}

// ---------------- masked softmax * window, then context ----------------------
__global__ void attctx_kernel(const float* __restrict__ enc, const int* __restrict__ masks) {
    int b = blockIdx.x;
    int tid = threadIdx.x;  // 256 == SS
    __shared__ float ws[SS];
    __shared__ float red[8];

    float e = g_energy[b * SS + tid];
    bool mk = masks[tid * BB + b] != 0;
    float val = mk ? e : -1e30f;

    float wm = warp_max(val);
    if ((tid & 31) == 0) red[tid >> 5] = wm;
    __syncthreads();
    float maxv = red[0];
    #pragma unroll
    for (int i = 1; i < 8; i++) maxv = fmaxf(maxv, red[i]);
    __syncthreads();

    float p = expf(val - maxv);
    float wsum = warp_sum(p);
    if ((tid & 31) == 0) red[tid >> 5] = wsum;
    __syncthreads();
    float sum = 0.f;
    #pragma unroll
    for (int i = 0; i < 8; i++) sum += red[i];

    float pt = g_pt[b];
    float sf = (float)tid;
    float diff = pt - sf;
    float win = expf(-(diff * diff) * (1.f / 12.5f));
    float pmaxf = floorf(pt + 5.0f);
    float pminf = floorf(fmaxf(pt - 5.0f, 0.0f));
    float w = (sf < pmaxf && sf >= pminf) ? (p / sum) * win : 0.f;
    ws[tid] = w;
    __syncthreads();

    int slo = (int)pminf;
    int shi = min((int)pmaxf, SS);
    for (int h = tid; h < HH; h += 256) {
        float acc = 0.f;
        for (int s = slo; s < shi; s++)
            acc += ws[s] * enc[((size_t)s * BB + b) * HH + h];
        g_ctx[b * HH + h] = acc;
    }
}

// ---------------- build gru_in = [x_emb, context] ----------------------------
__global__ void gruin_kernel() {
    int idx = blockIdx.x * blockDim.x + threadIdx.x;
    if (idx >= BB * KGI) return;
    int b = idx / KGI, k = idx - b * KGI;
    g_gruin[idx] = (k < EE) ? g_xemb[b * EE + k] : g_ctx[b * HH + (k - EE)];
}

// ---------------- GRU combine ------------------------------------------------
__global__ void gru_kernel(const float* __restrict__ phd, float* __restrict__ out,
                           int write_h) {
    int idx = blockIdx.x * blockDim.x + threadIdx.x;
    if (idx >= BB * HH) return;
    int b = idx / HH, h = idx - b * HH;
    const float* gi = g_gi + b * 3 * HH;
    const float* gh = g_gh + b * 3 * HH;
    float r  = 1.f / (1.f + expf(-(gi[h] + gh[h])));
    float zg = 1.f / (1.f + expf(-(gi[HH + h] + gh[HH + h])));
    float n  = tanhf(gi[2 * HH + h] + r * gh[2 * HH + h]);
    float hp = phd[idx];
    float hn = (1.f - zg) * n + zg * hp;
    g_incat[b * KFC + EE + h] = hn;
    if (write_h) out[(size_t)BB * VV + idx] = hn;
}

// ---------------- fill incat x_emb + context parts ---------------------------
__global__ void incat_kernel() {
    int idx = blockIdx.x * blockDim.x + threadIdx.x;
    if (idx >= BB * (EE + HH)) return;
    int b = idx / (EE + HH), k = idx - b * (EE + HH);
    if (k < EE) g_incat[b * KFC + k] = g_xemb[b * EE + k];
    else        g_incat[b * KFC + EE + HH + (k - EE)] = g_ctx[b * HH + (k - EE)];
}

// ---------------- launch -----------------------------------------------------
extern "C" void kernel_launch(void* const* d_in, const int* in_sizes, int n_in,
                              void* d_out, int out_size) {
    const int*   x      = (const int*)d_in[0];
    const float* phd    = (const float*)d_in[1];
    const float* enc    = (const float*)d_in[2];
    const int*   masks  = (const int*)d_in[3];
    const float* emb    = (const float*)d_in[4];
    const float* W_dec  = (const float*)d_in[5];
    const float* b_dec  = (const float*)d_in[6];
    const float* W_pos  = (const float*)d_in[7];
    const float* b_pos  = (const float*)d_in[8];
    const float* w_proj = (const float*)d_in[9];
    const float* W_ih   = (const float*)d_in[10];
    const float* b_ih   = (const float*)d_in[11];
    const float* W_hh   = (const float*)d_in[12];
    const float* b_hh   = (const float*)d_in[13];
    const float* W_fc   = (const float*)d_in[14];
    const float* b_fc   = (const float*)d_in[15];
    float* out = (float*)d_out;

    float* dwp;    cudaGetSymbolAddress((void**)&dwp, g_dw);
    float* tpartp; cudaGetSymbolAddress((void**)&tpartp, g_tpart);
    float* gruinp; cudaGetSymbolAddress((void**)&gruinp, g_gruin);
    float* gip;    cudaGetSymbolAddress((void**)&gip, g_gi);
    float* ghp;    cudaGetSymbolAddress((void**)&ghp, g_gh);
    float* incatp; cudaGetSymbolAddress((void**)&incatp, g_incat);
    __nv_bfloat16 *phdH, *phdL, *gruH, *gruL, *incH, *incL;
    cudaGetSymbolAddress((void**)&phdH, g_phdH);
    cudaGetSymbolAddress((void**)&phdL, g_phdL);
    cudaGetSymbolAddress((void**)&gruH, g_gruinH);
    cudaGetSymbolAddress((void**)&gruL, g_gruinL);
    cudaGetSymbolAddress((void**)&incH, g_incatH);
    cudaGetSymbolAddress((void**)&incL, g_incatL);

    cudaFuncSetAttribute(mma_gemm_kernel, cudaFuncAttributeMaxDynamicSharedMemorySize, SMEM_MMA);

    int write_h = (out_size >= BB * VV + BB * HH) ? 1 : 0;

    gather_kernel<<<(BB * EE + 255) / 256, 256>>>(x, emb);

    // split phd -> bf16 hi/lo
    conv_a_kernel<<<(BB * HH / 2 + 255) / 256, 256>>>(phd, phdH, phdL, BB * HH / 2);

    // dw = phd @ W_dec^T (mma); tpos = tanh(phd @ W_pos^T) (exact fp32 split-K)
    mma_gemm_kernel<<<HH / 128, 256, SMEM_MMA>>>(phdH, phdL, W_dec, b_dec, dwp, HH, HH);
    gemm_part_kernel<<<dim3(HH / 64, BB / 64, 4), 256>>>(phd, W_pos, tpartp, BB, HH, HH);
    reduce_tanh_kernel<<<(BB * HH + 255) / 256, 256>>>(b_pos);

    pt_kernel<<<BB, 256>>>(w_proj, masks);
    energy_kernel<<<dim3(SS, BB), 128>>>(enc);
    attctx_kernel<<<BB, SS>>>(enc, masks);

    gruin_kernel<<<(BB * KGI + 255) / 256, 256>>>();
    conv_a_kernel<<<(BB * KGI / 2 + 255) / 256, 256>>>(gruinp, gruH, gruL, BB * KGI / 2);
    mma_gemm_kernel<<<3 * HH / 128, 256, SMEM_MMA>>>(gruH, gruL, W_ih, b_ih, gip, 3 * HH, KGI);
    mma_gemm_kernel<<<3 * HH / 128, 256, SMEM_MMA>>>(phdH, phdL, W_hh, b_hh, ghp, 3 * HH, HH);

    gru_kernel<<<(BB * HH + 255) / 256, 256>>>(phd, out, write_h);
    incat_kernel<<<(BB * (EE + HH) + 255) / 256, 256>>>();
    conv_a_kernel<<<(BB * KFC / 2 + 255) / 256, 256>>>(incatp, incH, incL, BB * KFC / 2);

    // z = incat @ W_fc^T + b_fc  (dominant, pipelined bf16 3-term)
    mma_gemm_kernel<<<VV / 128, 256, SMEM_MMA>>>(incH, incL, W_fc, b_fc, out, VV, KFC);
}